// round 12
// baseline (speedup 1.0000x reference)
#include <cuda_runtime.h>
#include <cstdint>

// ---------------------------------------------------------------------------
// 4-layer LSTM (B=128, T=1024, D=128, H=[100,100,200,200]) + dense head.
// R10: scans redesigned around warp-shuffle gate reduction:
//   scan100: thread=(j,gate) owns a full K=100 dot; 3 SHFL gathers the gates;
//            ONE __syncthreads per step (h double-buffered in smem).
//   scan200: thread=(K-quarter, jl, gate-pair); shfl_xor reduces kh + gates;
//            NO __syncthreads in the loop — only the R7 st.async/mbarrier.
// GEMMs = R7 scalar fp32 (proven). Dense unchanged.
// ---------------------------------------------------------------------------

#define TLEN 1024
#define BSZ  128
#define HPAD 256

typedef unsigned long long u64;

__device__ float g_zx[(size_t)BSZ * TLEN * 800];  // x@Wx+b, layout [b][t][j][4]
__device__ float g_seq[(size_t)BSZ * TLEN * 200]; // layer output sequence
__device__ float g_hbuf[BSZ * HPAD];              // final h for dense head

#define FMA2(d, a, b, c) \
    asm("fma.rn.f32x2 %0, %1, %2, %3;" : "=l"(d) : "l"(a), "l"(b), "l"(c))

__device__ __forceinline__ u64 pack2(float lo, float hi) {
    u64 d;
    asm("mov.b64 %0, {%1, %2};" : "=l"(d)
        : "r"(__float_as_uint(lo)), "r"(__float_as_uint(hi)));
    return d;
}
__device__ __forceinline__ float2 unpack2(u64 v) {
    unsigned lo, hi;
    asm("mov.b64 {%0, %1}, %2;" : "=r"(lo), "=r"(hi) : "l"(v));
    return make_float2(__uint_as_float(lo), __uint_as_float(hi));
}

__device__ __forceinline__ float sigm(float x) {
    return __fdividef(1.0f, 1.0f + __expf(-x));
}
__device__ __forceinline__ float tanh_fast(float x) {
    return 1.0f - __fdividef(2.0f, __expf(2.0f * x) + 1.0f);
}

__device__ __forceinline__ void mbar_wait_parity_cluster(uint32_t bar, uint32_t parity) {
    uint32_t done;
    asm volatile(
        "{\n\t.reg .pred p;\n\t"
        "mbarrier.try_wait.parity.acquire.cluster.shared::cta.b64 p, [%1], %2;\n\t"
        "selp.b32 %0, 1, 0, p;\n\t}"
        : "=r"(done) : "r"(bar), "r"(parity) : "memory");
    if (!done) {
        asm volatile(
            "{\n\t.reg .pred P1;\n\t"
            "WAIT_LOOP_%=:\n\t"
            "mbarrier.try_wait.parity.acquire.cluster.shared::cta.b64 P1, [%0], %1, 0x989680;\n\t"
            "@P1 bra.uni WAIT_DONE_%=;\n\t"
            "bra.uni WAIT_LOOP_%=;\n\t"
            "WAIT_DONE_%=:\n\t}"
            :: "r"(bar), "r"(parity) : "memory");
    }
}

// ---------------------------------------------------------------------------
// Precompute GEMM (R7 scalar, proven): C[M,n] = A@W[.,colmap(n)] + bias.
// colmap(n) = (n&3)*Hn + (n>>2). 128x128 tile, 256 thr, 8x8 f32x2 tile,
// KC=8 double-buffered.
// ---------------------------------------------------------------------------
template <int K>
__global__ void __launch_bounds__(256, 2)
gemm_x(const float* __restrict__ Ain, const float* __restrict__ W,
       const float* __restrict__ bias, int N, int Hn, int use_seq)
{
    constexpr int KC = 8;
    constexpr int NCHUNK = (K + KC - 1) / KC;

    __shared__ __align__(16) float A_s[2][KC][132];
    __shared__ __align__(16) float W_s[2][KC][132];

    const float* __restrict__ A = use_seq ? g_seq : Ain;
    const int tid = threadIdx.x;
    const int tx = tid & 15, ty = tid >> 4;
    const int m0 = blockIdx.y * 128, n0 = blockIdx.x * 128;

    const int a_row = tid >> 3, a_kk = tid & 7;
    const int w_kk0 = tid >> 7, w_n = tid & 127;
    const int wcol  = n0 + w_n;
    const int wsrc  = (wcol & 3) * Hn + (wcol >> 2);

    float aR[4], wR[4];

    auto ldA = [&](int c) {
        const int k0 = c * KC;
        #pragma unroll
        for (int e = 0; e < 4; ++e) {
            int row = a_row + 32 * e;
            aR[e] = (k0 + a_kk < K) ? A[(size_t)(m0 + row) * K + k0 + a_kk] : 0.0f;
        }
    };
    auto ldW = [&](int c) {
        const int k0 = c * KC;
        #pragma unroll
        for (int e = 0; e < 4; ++e) {
            int kk = 2 * e + w_kk0;
            float v = 0.0f;
            if ((k0 + kk < K) && (wcol < N)) v = W[(size_t)(k0 + kk) * N + wsrc];
            wR[e] = v;
        }
    };
    auto stA = [&](int buf) {
        #pragma unroll
        for (int e = 0; e < 4; ++e) A_s[buf][a_kk][a_row + 32 * e] = aR[e];
    };
    auto stW = [&](int buf) {
        #pragma unroll
        for (int e = 0; e < 4; ++e) W_s[buf][2 * e + w_kk0][w_n] = wR[e];
    };

    ldA(0); ldW(0);
    stA(0); stW(0);
    __syncthreads();

    u64 acc2[4][8];
    #pragma unroll
    for (int mp = 0; mp < 4; ++mp)
        #pragma unroll
        for (int j = 0; j < 8; ++j) acc2[mp][j] = 0ull;

    for (int c = 0; c < NCHUNK; ++c) {
        const int buf = c & 1;
        if (c + 1 < NCHUNK) { ldA(c + 1); ldW(c + 1); }
        #pragma unroll
        for (int k = 0; k < KC; ++k) {
            ulonglong2 ap0 = *reinterpret_cast<const ulonglong2*>(&A_s[buf][k][ty * 8]);
            ulonglong2 ap1 = *reinterpret_cast<const ulonglong2*>(&A_s[buf][k][ty * 8 + 4]);
            float4 w0 = *reinterpret_cast<const float4*>(&W_s[buf][k][tx * 8]);
            float4 w1 = *reinterpret_cast<const float4*>(&W_s[buf][k][tx * 8 + 4]);
            u64 ap[4] = {ap0.x, ap0.y, ap1.x, ap1.y};
            u64 wd[8];
            wd[0] = pack2(w0.x, w0.x); wd[1] = pack2(w0.y, w0.y);
            wd[2] = pack2(w0.z, w0.z); wd[3] = pack2(w0.w, w0.w);
            wd[4] = pack2(w1.x, w1.x); wd[5] = pack2(w1.y, w1.y);
            wd[6] = pack2(w1.z, w1.z); wd[7] = pack2(w1.w, w1.w);
            #pragma unroll
            for (int mp = 0; mp < 4; ++mp)
                #pragma unroll
                for (int j = 0; j < 8; ++j)
                    FMA2(acc2[mp][j], ap[mp], wd[j], acc2[mp][j]);
        }
        if (c + 1 < NCHUNK) { stA(buf ^ 1); stW(buf ^ 1); }
        __syncthreads();
    }

    float accf[8][8];
    #pragma unroll
    for (int mp = 0; mp < 4; ++mp)
        #pragma unroll
        for (int j = 0; j < 8; ++j) {
            float2 t = unpack2(acc2[mp][j]);
            accf[2 * mp][j]     = t.x;
            accf[2 * mp + 1][j] = t.y;
        }

    if (n0 + tx * 8 < N) {
        float b[8];
        #pragma unroll
        for (int j = 0; j < 8; ++j) {
            int cc = n0 + tx * 8 + j;
            b[j] = bias[(cc & 3) * Hn + (cc >> 2)];
        }
        #pragma unroll
        for (int i = 0; i < 8; ++i) {
            size_t off = (size_t)(m0 + ty * 8 + i) * N + (n0 + tx * 8);
            float4 v0 = make_float4(accf[i][0] + b[0], accf[i][1] + b[1],
                                    accf[i][2] + b[2], accf[i][3] + b[3]);
            float4 v1 = make_float4(accf[i][4] + b[4], accf[i][5] + b[5],
                                    accf[i][6] + b[6], accf[i][7] + b[7]);
            *reinterpret_cast<float4*>(&g_zx[off])     = v0;
            *reinterpret_cast<float4*>(&g_zx[off + 4]) = v1;
        }
    }
}

// ---------------------------------------------------------------------------
// H=100 scan: 1 CTA / batch row, 448 threads. Thread (j<100, g<4) = tid
// computes the FULL K=100 dot for its (column, gate); 4 gate lanes are
// adjacent in a warp -> 4 SHFL gathers; lane g==0 does activations and owns
// c[j]. h double-buffered in smem: ONE __syncthreads per step.
// ---------------------------------------------------------------------------
__global__ void __launch_bounds__(448, 1)
scan100(const float* __restrict__ Wh)
{
    __shared__ __align__(16) float h_s[2][104];

    const int tid = threadIdx.x;
    const int b   = blockIdx.x;
    const int j   = tid >> 2;
    const int g   = tid & 3;
    const bool act = (tid < 400);
    const unsigned FULL = 0xFFFFFFFFu;
    const int lb  = (tid & 31) & ~3;

    u64 w2[50];                       // k-paired weights for (j, g)
    if (act) {
        #pragma unroll
        for (int kp = 0; kp < 50; ++kp)
            w2[kp] = pack2(Wh[(2 * kp)     * 400 + g * 100 + j],
                           Wh[(2 * kp + 1) * 400 + g * 100 + j]);
    }
    if (act && g == 0) h_s[0][j] = 0.0f;
    float c = 0.0f;
    __syncthreads();

    const float* __restrict__ zbase = g_zx + (size_t)b * TLEN * 400;
    float* __restrict__ ybase = g_seq + (size_t)b * TLEN * 100;

    // zx: one scalar per thread per step (tid == j*4+g matches [j][4] layout),
    // 2-deep register prefetch ring.
    float zr0 = 0.f, zr1 = 0.f;
    if (act) { zr0 = zbase[tid]; zr1 = zbase[400 + tid]; }

    for (int t = 0; t < TLEN; ++t) {
        const int cur = t & 1;
        float zc = (t & 1) ? zr1 : zr0;
        if (act) {
            int tp = (t + 2 < TLEN) ? t + 2 : t;
            float nv = zbase[(size_t)tp * 400 + tid];
            if (t & 1) zr1 = nv; else zr0 = nv;
        }
        float z = 0.0f;
        if (act) {
            u64 a0 = 0ull, a1 = 0ull;
            const ulonglong2* hp = reinterpret_cast<const ulonglong2*>(h_s[cur]);
            #pragma unroll
            for (int q = 0; q < 25; ++q) {
                ulonglong2 hv = hp[q];
                FMA2(a0, hv.x, w2[2 * q],     a0);
                FMA2(a1, hv.y, w2[2 * q + 1], a1);
            }
            float2 p0 = unpack2(a0), p1 = unpack2(a1);
            z = zc + p0.x + p0.y + p1.x + p1.y;
        }
        // gather the 4 gates of column j (adjacent lanes)
        float z0 = __shfl_sync(FULL, z, lb + 0);
        float z1 = __shfl_sync(FULL, z, lb + 1);
        float z2 = __shfl_sync(FULL, z, lb + 2);
        float z3 = __shfl_sync(FULL, z, lb + 3);
        if (act && g == 0) {
            float gi = sigm(z0), gf = sigm(z1), gg = tanh_fast(z2), go = sigm(z3);
            c = gf * c + gi * gg;
            float h = go * tanh_fast(c);
            h_s[cur ^ 1][j] = h;
            ybase[(size_t)t * 100 + j] = h;
        }
        __syncthreads();
    }
}

// ---------------------------------------------------------------------------
// H=200 scan: cluster of 4 CTAs; rank owns j-slice [50r,50r+50); cluster owns
// 4 batch rows. Thread (kh<4, jl<50, g2<2): K-quarter x gate-pair x all 4
// rows. Lane = (jl%4)*8 + g2*4 + kh -> shfl_xor reduces kh (x1, x2) and
// gathers the other gate-pair (x4). Lane (g2==0, kh==r) owns row r's
// activation + c state. h double-buffered; step sync = st.async + mbarrier
// only (NO __syncthreads in the loop).
// ---------------------------------------------------------------------------
template <int WRITE_Y>
__global__ void __launch_bounds__(448, 1) __cluster_dims__(4, 1, 1)
scan200(const float* __restrict__ Wh)
{
    __shared__ __align__(16) float h_s[2][4][208];   // [buf][row][k]
    __shared__ __align__(8)  u64   hbar;

    const int tid = threadIdx.x;
    uint32_t rank;
    asm("mov.u32 %0, %%cluster_ctarank;" : "=r"(rank));
    const int cl   = blockIdx.x >> 2;
    const int lane = tid & 31;
    const int jl   = (tid >> 5) * 4 + (lane >> 3);
    const int g2   = (lane >> 2) & 1;
    const int kh   = lane & 3;
    const bool act  = (jl < 50);
    const bool actv = act && (g2 == 0);
    const int jg   = (int)rank * 50 + jl;
    const int brow = cl * 4 + kh;          // batch row owned by activ lane
    const unsigned FULL = 0xFFFFFFFFu;

    uint32_t hs_addr, bar_addr;
    {
        const void* p = (const void*)&h_s[0][0][0];
        asm("{ .reg .u64 t; cvta.to.shared.u64 t, %1; cvt.u32.u64 %0, t; }"
            : "=r"(hs_addr) : "l"(p));
        const void* q = (const void*)&hbar;
        asm("{ .reg .u64 t; cvta.to.shared.u64 t, %1; cvt.u32.u64 %0, t; }"
            : "=r"(bar_addr) : "l"(q));
    }

    // k-paired weights for (kh quarter, gates 2*g2, 2*g2+1, column jg)
    u64 w2[25][2];
    if (act) {
        const int k0 = kh * 50;
        #pragma unroll
        for (int kp = 0; kp < 25; ++kp)
            #pragma unroll
            for (int gg = 0; gg < 2; ++gg) {
                const int gidx = 2 * g2 + gg;
                w2[kp][gg] = pack2(Wh[(k0 + 2 * kp)     * 800 + gidx * 200 + jg],
                                   Wh[(k0 + 2 * kp + 1) * 800 + gidx * 200 + jg]);
            }
    }
    for (int i = tid; i < 2 * 4 * 208; i += 448) (&h_s[0][0][0])[i] = 0.0f;
    if (tid == 0) {
        asm volatile("mbarrier.init.shared.b64 [%0], %1;"
                     :: "r"(bar_addr), "r"(1u) : "memory");
    }
    float c = 0.0f;
    __syncthreads();
    asm volatile("barrier.cluster.arrive.aligned;" ::: "memory");
    asm volatile("barrier.cluster.wait.aligned;" ::: "memory");

    const float* __restrict__ zxb = g_zx + (size_t)brow * TLEN * 800;
    float* __restrict__ ybase = g_seq + (size_t)brow * TLEN * 200;

    float4 zr0 = make_float4(0, 0, 0, 0), zr1 = zr0;
    if (actv) {
        zr0 = *reinterpret_cast<const float4*>(zxb + jg * 4);
        zr1 = *reinterpret_cast<const float4*>(zxb + 800 + jg * 4);
    }

    constexpr uint32_t TX_BYTES = 4u * 200u * 4u;   // 4 source CTAs x 200 floats

    for (int t = 0; t < TLEN; ++t) {
        const int cur = t & 1;
        if (tid == 0) {
            asm volatile("mbarrier.arrive.expect_tx.shared.b64 _, [%0], %1;"
                         :: "r"(bar_addr), "r"(TX_BYTES) : "memory");
        }
        float4 zc = (t & 1) ? zr1 : zr0;
        if (actv) {
            int tp = (t + 2 < TLEN) ? t + 2 : t;
            float4 nv = *reinterpret_cast<const float4*>(zxb + (size_t)tp * 800 + jg * 4);
            if (t & 1) zr1 = nv; else zr0 = nv;
        }

        float zaf[4] = {0, 0, 0, 0}, zbf[4] = {0, 0, 0, 0};
        if (act) {
            #pragma unroll
            for (int r2 = 0; r2 < 4; ++r2) {
                u64 aA = 0ull, aB = 0ull;
                const u64* hrow =
                    reinterpret_cast<const u64*>(&h_s[cur][r2][0]) + kh * 25;
                #pragma unroll
                for (int kp = 0; kp < 25; ++kp) {
                    u64 hv = hrow[kp];
                    FMA2(aA, hv, w2[kp][0], aA);
                    FMA2(aB, hv, w2[kp][1], aB);
                }
                float2 pA = unpack2(aA), pB = unpack2(aB);
                zaf[r2] = pA.x + pA.y;
                zbf[r2] = pB.x + pB.y;
            }
        }

        // reduce kh quarters (xor 1, 2) and gather the other gate-pair (xor 4)
        float z0 = 0.f, z1 = 0.f, z2 = 0.f, z3 = 0.f;
        #pragma unroll
        for (int r = 0; r < 4; ++r) {
            float a  = zaf[r], bq = zbf[r];
            a  += __shfl_xor_sync(FULL, a, 1);
            a  += __shfl_xor_sync(FULL, a, 2);
            bq += __shfl_xor_sync(FULL, bq, 1);
            bq += __shfl_xor_sync(FULL, bq, 2);
            float cg = __shfl_xor_sync(FULL, a, 4);
            float dg = __shfl_xor_sync(FULL, bq, 4);
            if (kh == r) { z0 = a; z1 = bq; z2 = cg; z3 = dg; }
        }

        if (actv) {
            z0 += zc.x; z1 += zc.y; z2 += zc.z; z3 += zc.w;
            float gi = sigm(z0), gf = sigm(z1), gg = tanh_fast(z2), go = sigm(z3);
            c = gf * c + gi * gg;
            float h = go * tanh_fast(c);

            const int nxt = cur ^ 1;
            uint32_t laddr = hs_addr + (uint32_t)((nxt * 4 + kh) * 208 + jg) * 4u;
            #pragma unroll
            for (int p = 0; p < 4; ++p) {
                uint32_t rdata, rbar;
                asm("mapa.shared::cluster.u32 %0, %1, %2;"
                    : "=r"(rdata) : "r"(laddr), "r"(p));
                asm("mapa.shared::cluster.u32 %0, %1, %2;"
                    : "=r"(rbar) : "r"(bar_addr), "r"(p));
                asm volatile(
                    "st.async.shared::cluster.mbarrier::complete_tx::bytes.f32 "
                    "[%0], %1, [%2];"
                    :: "r"(rdata), "f"(h), "r"(rbar) : "memory");
            }
            if (WRITE_Y) ybase[(size_t)t * 200 + jg] = h;
            if (t == TLEN - 1) g_hbuf[brow * HPAD + jg] = h;
        }
        mbar_wait_parity_cluster(bar_addr, (uint32_t)(t & 1));
    }

    asm volatile("barrier.cluster.arrive.aligned;" ::: "memory");
    asm volatile("barrier.cluster.wait.aligned;" ::: "memory");
}

// Final dense: out[b, o] = h_last[b, :200] @ Wd + bd.
__global__ void dense_kernel(const float* __restrict__ Wd,
                             const float* __restrict__ bd,
                             float* __restrict__ out)
{
    int idx = blockIdx.x * blockDim.x + threadIdx.x;
    if (idx >= BSZ * 6) return;
    int b = idx / 6, o = idx - b * 6;
    const float* h = g_hbuf + b * HPAD;
    float s = bd[o];
    #pragma unroll 8
    for (int k = 0; k < 200; ++k) s += h[k] * Wd[k * 6 + o];
    out[idx] = s;
}

extern "C" void kernel_launch(void* const* d_in, const int* in_sizes, int n_in,
                              void* d_out, int out_size)
{
    const float* xs  = (const float*)d_in[0];
    const float* Wx0 = (const float*)d_in[1];
    const float* Wh0 = (const float*)d_in[2];
    const float* b0  = (const float*)d_in[3];
    const float* Wx1 = (const float*)d_in[4];
    const float* Wh1 = (const float*)d_in[5];
    const float* b1  = (const float*)d_in[6];
    const float* Wx2 = (const float*)d_in[7];
    const float* Wh2 = (const float*)d_in[8];
    const float* b2  = (const float*)d_in[9];
    const float* Wx3 = (const float*)d_in[10];
    const float* Wh3 = (const float*)d_in[11];
    const float* b3  = (const float*)d_in[12];
    const float* Wd  = (const float*)d_in[13];
    const float* bd  = (const float*)d_in[14];

    const dim3 gN400(4, 1024);   // ceil(400/128) x (131072/128)
    const dim3 gN800(7, 1024);   // ceil(800/128)

    // L0
    gemm_x<128><<<gN400, 256>>>(xs, Wx0, b0, 400, 100, 0);
    scan100<<<BSZ, 448>>>(Wh0);
    // L1
    gemm_x<100><<<gN400, 256>>>(nullptr, Wx1, b1, 400, 100, 1);
    scan100<<<BSZ, 448>>>(Wh1);
    // L2
    gemm_x<100><<<gN800, 256>>>(nullptr, Wx2, b2, 800, 200, 1);
    scan200<1><<<BSZ, 448>>>(Wh2);
    // L3
    gemm_x<200><<<gN800, 256>>>(nullptr, Wx3, b3, 800, 200, 1);
    scan200<0><<<BSZ, 448>>>(Wh3);
    // head
    dense_kernel<<<3, 256>>>(Wd, bd, (float*)d_out);
}

// round 14
// speedup vs baseline: 1.5908x; 1.5908x over previous
#include <cuda_runtime.h>
#include <cstdint>

// ---------------------------------------------------------------------------
// 4-layer LSTM (B=128, T=1024, D=128, H=[100,100,200,200]) + dense head.
// R13: R12's bf16 tensor-core GEMM with the SMEM stride alignment fix
// (LDQ 9 -> 10: 40-byte row stride keeps every uint2 fragment load 8B
// aligned; LDQ=9's 36-byte stride trapped with "misaligned address").
// Scans identical to R7 (7863us baseline).
// ---------------------------------------------------------------------------

#define TLEN 1024
#define BSZ  128
#define HPAD 256

typedef unsigned long long u64;
typedef unsigned int u32;

__device__ float g_zx[(size_t)BSZ * TLEN * 800];  // x@Wx+b, layout [b][t][j][4]
__device__ float g_seq[(size_t)BSZ * TLEN * 200]; // layer output sequence
__device__ float g_hbuf[BSZ * HPAD];              // final h for dense head

#define FMA2(d, a, b, c) \
    asm("fma.rn.f32x2 %0, %1, %2, %3;" : "=l"(d) : "l"(a), "l"(b), "l"(c))

__device__ __forceinline__ u64 pack2(float lo, float hi) {
    u64 d;
    asm("mov.b64 %0, {%1, %2};" : "=l"(d)
        : "r"(__float_as_uint(lo)), "r"(__float_as_uint(hi)));
    return d;
}
__device__ __forceinline__ float2 unpack2(u64 v) {
    unsigned lo, hi;
    asm("mov.b64 {%0, %1}, %2;" : "=r"(lo), "=r"(hi) : "l"(v));
    return make_float2(__uint_as_float(lo), __uint_as_float(hi));
}

__device__ __forceinline__ float sigm(float x) {
    return __fdividef(1.0f, 1.0f + __expf(-x));
}
__device__ __forceinline__ float tanh_fast(float x) {
    return 1.0f - __fdividef(2.0f, __expf(2.0f * x) + 1.0f);
}

__device__ __forceinline__ void mbar_wait_parity_cluster(uint32_t bar, uint32_t parity) {
    uint32_t done;
    asm volatile(
        "{\n\t.reg .pred p;\n\t"
        "mbarrier.try_wait.parity.acquire.cluster.shared::cta.b64 p, [%1], %2;\n\t"
        "selp.b32 %0, 1, 0, p;\n\t}"
        : "=r"(done) : "r"(bar), "r"(parity) : "memory");
    if (!done) {
        asm volatile(
            "{\n\t.reg .pred P1;\n\t"
            "WAIT_LOOP_%=:\n\t"
            "mbarrier.try_wait.parity.acquire.cluster.shared::cta.b64 P1, [%0], %1, 0x989680;\n\t"
            "@P1 bra.uni WAIT_DONE_%=;\n\t"
            "bra.uni WAIT_LOOP_%=;\n\t"
            "WAIT_DONE_%=:\n\t}"
            :: "r"(bar), "r"(parity) : "memory");
    }
}

// ---------------------------------------------------------------------------
// bf16 helpers
// ---------------------------------------------------------------------------
__device__ __forceinline__ u32 bf16x2_of(float f0, float f1) {
    u32 r;   // f0 -> low half, f1 -> high half
    asm("cvt.rn.bf16x2.f32 %0, %1, %2;" : "=r"(r) : "f"(f1), "f"(f0));
    return r;
}
__device__ __forceinline__ float bf_lo_f(u32 v) { return __uint_as_float(v << 16); }
__device__ __forceinline__ float bf_hi_f(u32 v) { return __uint_as_float(v & 0xffff0000u); }

__device__ __forceinline__ void mma_bf16(float* c, const u32* a, const u32* b) {
    asm volatile(
        "mma.sync.aligned.m16n8k16.row.col.f32.bf16.bf16.f32 "
        "{%0,%1,%2,%3}, {%4,%5,%6,%7}, {%8,%9}, {%0,%1,%2,%3};"
        : "+f"(c[0]), "+f"(c[1]), "+f"(c[2]), "+f"(c[3])
        : "r"(a[0]), "r"(a[1]), "r"(a[2]), "r"(a[3]), "r"(b[0]), "r"(b[1]));
}

// ---------------------------------------------------------------------------
// bf16 tensor-core precompute GEMM (3-term hi/lo split: hh + lh + hl).
// C[M=BSZ*TLEN, n] = A[M,K] @ W[K, colmap(n)] + bias[colmap(n)] -> g_zx,
// colmap(n) = (n&3)*Hn + (n>>2)  (gate-interleaved layout for the scans).
// 128x128 CTA tile, 256 threads, 8 warps (32x64), KC=16 double-buffered.
// SMEM planes hold bf16x2 k-pairs, permuted p(k2)=(k2&3)*2+(k2>>2) so each
// mma fragment is one 8B LDS; row stride LDQ=10 u32 (40B: 8B-aligned rows).
// ---------------------------------------------------------------------------
template <int K>
__global__ void __launch_bounds__(256, 2)
gemm_bf16(const float* __restrict__ Ain, const float* __restrict__ W,
          const float* __restrict__ bias, int N, int Hn, int use_seq)
{
    constexpr int KC  = 16;
    constexpr int NCH = (K + KC - 1) / KC;
    constexpr int LDQ = 10;                   // u32 stride per row (8 + pad, 8B-aligned)

    __shared__ __align__(16) u32 Ah[2][128][LDQ], Al[2][128][LDQ];
    __shared__ __align__(16) u32 Bh[2][128][LDQ], Bl[2][128][LDQ];

    const float* __restrict__ A = use_seq ? g_seq : Ain;
    const int tid  = threadIdx.x;
    const int m0   = blockIdx.y * 128, n0 = blockIdx.x * 128;
    const int warp = tid >> 5, lane = tid & 31;
    const int g    = lane >> 2, tig = lane & 3;
    const int wm   = (warp >> 1) * 32, wn = (warp & 1) * 64;

    // staging roles: d = row/col (tid>>1), half = k-half (tid&1: 8 k each)
    const int sd = tid >> 1, sh = tid & 1;
    const int wcol = n0 + sd;
    const int bsrc = (wcol & 3) * Hn + (wcol >> 2);    // permuted W column
    const bool bok = wcol < N;

    float aR[8], bR[8];

    auto ldA = [&](int c) {
        const int kb = c * KC + sh * 8;
        if (kb + 8 <= K) {
            float4 v0 = *reinterpret_cast<const float4*>(&A[(size_t)(m0 + sd) * K + kb]);
            float4 v1 = *reinterpret_cast<const float4*>(&A[(size_t)(m0 + sd) * K + kb + 4]);
            aR[0] = v0.x; aR[1] = v0.y; aR[2] = v0.z; aR[3] = v0.w;
            aR[4] = v1.x; aR[5] = v1.y; aR[6] = v1.z; aR[7] = v1.w;
        } else {
            #pragma unroll
            for (int e = 0; e < 8; ++e)
                aR[e] = (kb + e < K) ? A[(size_t)(m0 + sd) * K + kb + e] : 0.0f;
        }
    };
    auto ldB = [&](int c) {
        const int kb = c * KC + sh * 8;
        #pragma unroll
        for (int e = 0; e < 8; ++e) {
            float v = 0.0f;
            if ((kb + e < K) && bok) v = W[(size_t)(kb + e) * N + bsrc];
            bR[e] = v;
        }
    };
    auto stA = [&](int buf) {
        #pragma unroll
        for (int e = 0; e < 4; ++e) {
            int k2 = sh * 4 + e;
            int p  = (k2 & 3) * 2 + (k2 >> 2);
            u32 hi = bf16x2_of(aR[2 * e], aR[2 * e + 1]);
            float l0 = aR[2 * e]     - bf_lo_f(hi);
            float l1 = aR[2 * e + 1] - bf_hi_f(hi);
            Ah[buf][sd][p] = hi;
            Al[buf][sd][p] = bf16x2_of(l0, l1);
        }
    };
    auto stB = [&](int buf) {
        #pragma unroll
        for (int e = 0; e < 4; ++e) {
            int k2 = sh * 4 + e;
            int p  = (k2 & 3) * 2 + (k2 >> 2);
            u32 hi = bf16x2_of(bR[2 * e], bR[2 * e + 1]);
            float l0 = bR[2 * e]     - bf_lo_f(hi);
            float l1 = bR[2 * e + 1] - bf_hi_f(hi);
            Bh[buf][sd][p] = hi;
            Bl[buf][sd][p] = bf16x2_of(l0, l1);
        }
    };

    ldA(0); ldB(0);
    stA(0); stB(0);
    __syncthreads();

    float acc[2][8][4];
    #pragma unroll
    for (int mt = 0; mt < 2; ++mt)
        #pragma unroll
        for (int nt = 0; nt < 8; ++nt)
            #pragma unroll
            for (int i = 0; i < 4; ++i) acc[mt][nt][i] = 0.0f;

    for (int c = 0; c < NCH; ++c) {
        const int buf = c & 1;
        if (c + 1 < NCH) { ldA(c + 1); ldB(c + 1); }

        u32 ah[2][4], al[2][4];
        #pragma unroll
        for (int mt = 0; mt < 2; ++mt) {
            int row = wm + mt * 16 + g;
            uint2 t;
            t = *reinterpret_cast<const uint2*>(&Ah[buf][row][2 * tig]);
            ah[mt][0] = t.x; ah[mt][2] = t.y;
            t = *reinterpret_cast<const uint2*>(&Ah[buf][row + 8][2 * tig]);
            ah[mt][1] = t.x; ah[mt][3] = t.y;
            t = *reinterpret_cast<const uint2*>(&Al[buf][row][2 * tig]);
            al[mt][0] = t.x; al[mt][2] = t.y;
            t = *reinterpret_cast<const uint2*>(&Al[buf][row + 8][2 * tig]);
            al[mt][1] = t.x; al[mt][3] = t.y;
        }
        #pragma unroll
        for (int nt = 0; nt < 8; ++nt) {
            int coln = wn + nt * 8 + g;
            u32 bh[2], bl[2];
            uint2 t;
            t = *reinterpret_cast<const uint2*>(&Bh[buf][coln][2 * tig]);
            bh[0] = t.x; bh[1] = t.y;
            t = *reinterpret_cast<const uint2*>(&Bl[buf][coln][2 * tig]);
            bl[0] = t.x; bl[1] = t.y;
            #pragma unroll
            for (int mt = 0; mt < 2; ++mt) {
                mma_bf16(acc[mt][nt], ah[mt], bh);
                mma_bf16(acc[mt][nt], al[mt], bh);
                mma_bf16(acc[mt][nt], ah[mt], bl);
            }
        }
        if (c + 1 < NCH) { stA(buf ^ 1); stB(buf ^ 1); }
        __syncthreads();
    }

    // epilogue: bias (permuted) + store
    #pragma unroll
    for (int nt = 0; nt < 8; ++nt) {
        int col = n0 + wn + nt * 8 + tig * 2;
        if (col >= N) continue;
        float b0 = bias[(col & 3) * Hn + (col >> 2)];
        float b1 = bias[((col + 1) & 3) * Hn + ((col + 1) >> 2)];
        #pragma unroll
        for (int mt = 0; mt < 2; ++mt) {
            int row = m0 + wm + mt * 16 + g;
            float2 v0 = make_float2(acc[mt][nt][0] + b0, acc[mt][nt][1] + b1);
            float2 v1 = make_float2(acc[mt][nt][2] + b0, acc[mt][nt][3] + b1);
            *reinterpret_cast<float2*>(&g_zx[(size_t)row * N + col])       = v0;
            *reinterpret_cast<float2*>(&g_zx[(size_t)(row + 8) * N + col]) = v1;
        }
    }
}

// ---------------------------------------------------------------------------
// H=100 scan (R7, proven): 1 CTA per batch row, Wh in regs (k-paired f32x2),
// h in SMEM, zx float4 with 2-deep register prefetch ring.
// ---------------------------------------------------------------------------
__global__ void __launch_bounds__(512, 1)
scan100(const float* __restrict__ Wh)
{
    __shared__ __align__(16) float  h_s[104];
    __shared__ __align__(16) float4 zp[5][100];

    const int tid = threadIdx.x;
    const int b   = blockIdx.x;
    const int s   = tid / 100;
    const int j   = tid % 100;
    const bool ga  = (tid < 500);
    const bool red = (tid < 100);

    u64 w2[10][4];
    if (ga) {
        const int k0 = s * 20;
        #pragma unroll
        for (int kp = 0; kp < 10; ++kp)
            #pragma unroll
            for (int g = 0; g < 4; ++g)
                w2[kp][g] = pack2(Wh[(k0 + 2 * kp)     * 400 + g * 100 + j],
                                  Wh[(k0 + 2 * kp + 1) * 400 + g * 100 + j]);
    }
    if (red) h_s[j] = 0.0f;
    float c = 0.0f;
    __syncthreads();

    const float* __restrict__ zbase = g_zx + (size_t)b * TLEN * 400;
    float* __restrict__ ybase = g_seq + (size_t)b * TLEN * 100;

    float4 zb0 = make_float4(0, 0, 0, 0), zb1 = zb0;
    if (red) {
        zb0 = *reinterpret_cast<const float4*>(zbase + j * 4);
        zb1 = *reinterpret_cast<const float4*>(zbase + 400 + j * 4);
    }

    auto step = [&](int t, float4& zslot) {
        float4 zc;
        if (red) {
            zc = zslot;
            int tp = (t + 2 < TLEN) ? t + 2 : t;
            zslot = *reinterpret_cast<const float4*>(zbase + (size_t)tp * 400 + j * 4);
        }
        if (ga) {
            u64 a0 = 0ull, a1 = 0ull, a2 = 0ull, a3 = 0ull;
            const ulonglong2* hp = reinterpret_cast<const ulonglong2*>(h_s);
            const int qb = s * 5;
            #pragma unroll
            for (int q = 0; q < 5; ++q) {
                ulonglong2 hv = hp[qb + q];
                FMA2(a0, hv.x, w2[2 * q][0], a0);
                FMA2(a1, hv.x, w2[2 * q][1], a1);
                FMA2(a2, hv.x, w2[2 * q][2], a2);
                FMA2(a3, hv.x, w2[2 * q][3], a3);
                FMA2(a0, hv.y, w2[2 * q + 1][0], a0);
                FMA2(a1, hv.y, w2[2 * q + 1][1], a1);
                FMA2(a2, hv.y, w2[2 * q + 1][2], a2);
                FMA2(a3, hv.y, w2[2 * q + 1][3], a3);
            }
            float2 p0 = unpack2(a0), p1 = unpack2(a1), p2 = unpack2(a2), p3 = unpack2(a3);
            zp[s][j] = make_float4(p0.x + p0.y, p1.x + p1.y, p2.x + p2.y, p3.x + p3.y);
        }
        __syncthreads();
        if (red) {
            float z0 = zc.x, z1 = zc.y, z2 = zc.z, z3 = zc.w;
            #pragma unroll
            for (int ss = 0; ss < 5; ++ss) {
                float4 p = zp[ss][j];
                z0 += p.x; z1 += p.y; z2 += p.z; z3 += p.w;
            }
            float gi = sigm(z0), gf = sigm(z1), gg = tanh_fast(z2), go = sigm(z3);
            c = gf * c + gi * gg;
            float h = go * tanh_fast(c);
            h_s[j] = h;
            ybase[(size_t)t * 100 + j] = h;
        }
        __syncthreads();
    };

    for (int t = 0; t < TLEN; t += 2) {
        step(t,     zb0);
        step(t + 1, zb1);
    }
}

// ---------------------------------------------------------------------------
// H=200 scan (R7, proven): cluster of 4 CTAs; rank owns j-slice [50r,50r+50);
// cluster owns 4 batch rows. Wh slice in regs (k-paired f32x2); h double-
// buffered in SMEM; per-step sync = st.async tx-counted DSMEM broadcast +
// mbarrier parity wait.
// ---------------------------------------------------------------------------
template <int WRITE_Y>
__global__ void __launch_bounds__(512, 1) __cluster_dims__(4, 1, 1)
scan200(const float* __restrict__ Wh)
{
    __shared__ __align__(16) float  h_s[2][4][208];   // [buf][row][k]
    __shared__ __align__(16) float4 zp[10][4][50];    // [split][row][jl]
    __shared__ __align__(8)  u64    hbar;             // tx-counted mbarrier

    const int tid = threadIdx.x;
    uint32_t rank;
    asm("mov.u32 %0, %%cluster_ctarank;" : "=r"(rank));
    const int cl = blockIdx.x >> 2;

    const int s  = tid / 50;               // gemm split 0..9 (tid<500)
    const int jl = tid % 50;
    const bool ga  = (tid < 500);
    const bool red = (tid < 200);          // reduce row = s (0..3)
    const int  rr  = s;
    const int  jg  = (int)rank * 50 + jl;

    uint32_t hs_addr, bar_addr;
    {
        const void* p = (const void*)&h_s[0][0][0];
        asm("{ .reg .u64 t; cvta.to.shared.u64 t, %1; cvt.u32.u64 %0, t; }"
            : "=r"(hs_addr) : "l"(p));
        const void* q = (const void*)&hbar;
        asm("{ .reg .u64 t; cvta.to.shared.u64 t, %1; cvt.u32.u64 %0, t; }"
            : "=r"(bar_addr) : "l"(q));
    }

    u64 w2[10][4];   // [k-pair][gate] = {W[k][g][jg], W[k+1][g][jg]}
    if (ga) {
        const int k0 = s * 20;
        #pragma unroll
        for (int kp = 0; kp < 10; ++kp)
            #pragma unroll
            for (int g = 0; g < 4; ++g)
                w2[kp][g] = pack2(Wh[(k0 + 2 * kp)     * 800 + g * 200 + jg],
                                  Wh[(k0 + 2 * kp + 1) * 800 + g * 200 + jg]);
    }
    for (int i = tid; i < 2 * 4 * 208; i += 512) (&h_s[0][0][0])[i] = 0.0f;
    if (tid == 0) {
        asm volatile("mbarrier.init.shared.b64 [%0], %1;"
                     :: "r"(bar_addr), "r"(1u) : "memory");
    }
    float c = 0.0f;
    __syncthreads();
    asm volatile("barrier.cluster.arrive.aligned;" ::: "memory");
    asm volatile("barrier.cluster.wait.aligned;" ::: "memory");

    const int b = cl * 4 + rr;
    const float* __restrict__ zbase = g_zx + (size_t)b * TLEN * 800;
    float* __restrict__ ybase = g_seq + (size_t)b * TLEN * 200;

    float4 zb0 = make_float4(0, 0, 0, 0), zb1 = zb0;
    if (red) {
        zb0 = *reinterpret_cast<const float4*>(zbase + jg * 4);
        zb1 = *reinterpret_cast<const float4*>(zbase + 800 + jg * 4);
    }

    constexpr uint32_t TX_BYTES = 4u * 200u * 4u;   // 4 source CTAs x 200 floats

    auto step = [&](int t, float4& zslot, int cur) {
        if (tid == 0) {
            asm volatile("mbarrier.arrive.expect_tx.shared.b64 _, [%0], %1;"
                         :: "r"(bar_addr), "r"(TX_BYTES) : "memory");
        }
        float4 zc;
        if (red) {
            zc = zslot;
            int tp = (t + 2 < TLEN) ? t + 2 : t;
            zslot = *reinterpret_cast<const float4*>(zbase + (size_t)tp * 800 + jg * 4);
        }
        if (ga) {
            const int qb = s * 5;
            #pragma unroll
            for (int r2 = 0; r2 < 4; ++r2) {
                u64 a0 = 0ull, a1 = 0ull, a2 = 0ull, a3 = 0ull;
                const ulonglong2* hp =
                    reinterpret_cast<const ulonglong2*>(&h_s[cur][r2][0]);
                #pragma unroll
                for (int q = 0; q < 5; ++q) {
                    ulonglong2 hv = hp[qb + q];
                    FMA2(a0, hv.x, w2[2 * q][0], a0);
                    FMA2(a1, hv.x, w2[2 * q][1], a1);
                    FMA2(a2, hv.x, w2[2 * q][2], a2);
                    FMA2(a3, hv.x, w2[2 * q][3], a3);
                    FMA2(a0, hv.y, w2[2 * q + 1][0], a0);
                    FMA2(a1, hv.y, w2[2 * q + 1][1], a1);
                    FMA2(a2, hv.y, w2[2 * q + 1][2], a2);
                    FMA2(a3, hv.y, w2[2 * q + 1][3], a3);
                }
                float2 p0 = unpack2(a0), p1 = unpack2(a1),
                       p2 = unpack2(a2), p3 = unpack2(a3);
                zp[s][r2][jl] = make_float4(p0.x + p0.y, p1.x + p1.y,
                                            p2.x + p2.y, p3.x + p3.y);
            }
        }
        __syncthreads();
        if (red) {
            float z0 = zc.x, z1 = zc.y, z2 = zc.z, z3 = zc.w;
            #pragma unroll
            for (int ss = 0; ss < 10; ++ss) {
                float4 p = zp[ss][rr][jl];
                z0 += p.x; z1 += p.y; z2 += p.z; z3 += p.w;
            }
            float gi = sigm(z0), gf = sigm(z1), gg = tanh_fast(z2), go = sigm(z3);
            c = gf * c + gi * gg;
            float h = go * tanh_fast(c);

            const int nxt = cur ^ 1;
            uint32_t laddr = hs_addr + (uint32_t)((nxt * 4 + rr) * 208 + jg) * 4u;
            #pragma unroll
            for (int p = 0; p < 4; ++p) {
                uint32_t rdata, rbar;
                asm("mapa.shared::cluster.u32 %0, %1, %2;"
                    : "=r"(rdata) : "r"(laddr), "r"(p));
                asm("mapa.shared::cluster.u32 %0, %1, %2;"
                    : "=r"(rbar) : "r"(bar_addr), "r"(p));
                asm volatile(
                    "st.async.shared::cluster.mbarrier::complete_tx::bytes.f32 "
                    "[%0], %1, [%2];"
                    :: "r"(rdata), "f"(h), "r"(rbar) : "memory");
            }
            if (WRITE_Y) ybase[(size_t)t * 200 + jg] = h;
            if (t == TLEN - 1) g_hbuf[b * HPAD + jg] = h;
        }
        mbar_wait_parity_cluster(bar_addr, (uint32_t)(t & 1));
    };

    for (int t = 0; t < TLEN; t += 2) {
        step(t,     zb0, 0);
        step(t + 1, zb1, 1);
    }

    asm volatile("barrier.cluster.arrive.aligned;" ::: "memory");
    asm volatile("barrier.cluster.wait.aligned;" ::: "memory");
}

// Final dense: out[b, o] = h_last[b, :200] @ Wd + bd.
__global__ void dense_kernel(const float* __restrict__ Wd,
                             const float* __restrict__ bd,
                             float* __restrict__ out)
{
    int idx = blockIdx.x * blockDim.x + threadIdx.x;
    if (idx >= BSZ * 6) return;
    int b = idx / 6, o = idx - b * 6;
    const float* h = g_hbuf + b * HPAD;
    float s = bd[o];
    #pragma unroll 8
    for (int k = 0; k < 200; ++k) s += h[k] * Wd[k * 6 + o];
    out[idx] = s;
}

extern "C" void kernel_launch(void* const* d_in, const int* in_sizes, int n_in,
                              void* d_out, int out_size)
{
    const float* xs  = (const float*)d_in[0];
    const float* Wx0 = (const float*)d_in[1];
    const float* Wh0 = (const float*)d_in[2];
    const float* b0  = (const float*)d_in[3];
    const float* Wx1 = (const float*)d_in[4];
    const float* Wh1 = (const float*)d_in[5];
    const float* b1  = (const float*)d_in[6];
    const float* Wx2 = (const float*)d_in[7];
    const float* Wh2 = (const float*)d_in[8];
    const float* b2  = (const float*)d_in[9];
    const float* Wx3 = (const float*)d_in[10];
    const float* Wh3 = (const float*)d_in[11];
    const float* b3  = (const float*)d_in[12];
    const float* Wd  = (const float*)d_in[13];
    const float* bd  = (const float*)d_in[14];

    const dim3 gN400(4, 1024);   // ceil(400/128) x (131072/128)
    const dim3 gN800(7, 1024);   // ceil(800/128)

    // L0
    gemm_bf16<128><<<gN400, 256>>>(xs, Wx0, b0, 400, 100, 0);
    scan100<<<BSZ, 512>>>(Wh0);
    // L1
    gemm_bf16<100><<<gN400, 256>>>(nullptr, Wx1, b1, 400, 100, 1);
    scan100<<<BSZ, 512>>>(Wh1);
    // L2
    gemm_bf16<100><<<gN800, 256>>>(nullptr, Wx2, b2, 800, 200, 1);
    scan200<1><<<BSZ, 512>>>(Wh2);
    // L3
    gemm_bf16<200><<<gN800, 256>>>(nullptr, Wx3, b3, 800, 200, 1);
    scan200<0><<<BSZ, 512>>>(Wh3);
    // head
    dense_kernel<<<3, 256>>>(Wd, bd, (float*)d_out);
}